// round 9
// baseline (speedup 1.0000x reference)
#include <cuda_runtime.h>
#include <cuda_fp16.h>
#include <cstdint>

// Problem constants
constexpr int Bb  = 2;
constexpr int Cc  = 256;
constexpr int Hh  = 56;
constexpr int Ww  = 96;
constexpr int HWv = Hh * Ww;          // 5376
constexpr int Nn  = Bb * HWv;         // 10752

// Pyramid dims
constexpr int H1 = 28, W1 = 48;
constexpr int H2 = 14, W2 = 24;
constexpr int H3 = 7,  W3 = 12;

// fp16 channels-last maps: query map + fmap2 pyramid; compact corr scratch
__device__ __half g_f1h[(size_t)Bb * HWv * Cc];
__device__ __half g_f20[(size_t)Bb * HWv * Cc];
__device__ __half g_f21[(size_t)Bb * H1 * W1 * Cc];
__device__ __half g_f22[(size_t)Bb * H2 * W2 * Cc];
__device__ __half g_f23[(size_t)Bb * H3 * W3 * Cc];
__device__ float  g_corr[(size_t)Nn * 324];

// ---------------------------------------------------------------------------
// Transpose [B, C, HW] -> [B, HW, C] with fp32 -> fp16 convert
// which == 0 -> g_f1h (query map), which == 1 -> g_f20 (fmap2 level 0)
// ---------------------------------------------------------------------------
__global__ void transpose_h_k(const float* __restrict__ in, int which) {
    __shared__ float tile[32][33];
    __half* out = which ? g_f20 : g_f1h;
    int b   = blockIdx.z;
    int hw0 = blockIdx.x * 32;
    int c0  = blockIdx.y * 32;
    const float* ib = in  + (size_t)b * Cc * HWv;
    __half*      ob = out + (size_t)b * HWv * Cc;
    int tx = threadIdx.x, ty = threadIdx.y;   // 32 x 8
#pragma unroll
    for (int r = 0; r < 32; r += 8)
        tile[ty + r][tx] = ib[(size_t)(c0 + ty + r) * HWv + hw0 + tx];
    __syncthreads();
#pragma unroll
    for (int r = 0; r < 32; r += 8)
        ob[(size_t)(hw0 + ty + r) * Cc + c0 + tx] = __float2half_rn(tile[tx][ty + r]);
}

// ---------------------------------------------------------------------------
// 2x2 avg pool on channels-last fp16 layout. 128 threads = 128 half2 lanes.
// ---------------------------------------------------------------------------
__global__ void pool_k(int level) {
    const __half* in; __half* out; int Wi, Wo, Ho;
    if (level == 1)      { in = g_f20; out = g_f21; Wi = 96; Wo = 48; Ho = 28; }
    else if (level == 2) { in = g_f21; out = g_f22; Wi = 48; Wo = 24; Ho = 14; }
    else                 { in = g_f22; out = g_f23; Wi = 24; Wo = 12; Ho = 7;  }
    int HiWi = (2 * Ho) * Wi;
    int HoWo = Ho * Wo;
    int b = blockIdx.y, p = blockIdx.x, c = threadIdx.x;   // c in [0,128) half2 units
    int y = p / Wo, x = p - y * Wo;
    const __half2* ib = (const __half2*)(in + (size_t)b * HiWi * Cc);
    size_t i00 = ((size_t)(2 * y) * Wi + 2 * x) * (Cc / 2) + c;
    size_t rs  = (size_t)Wi * (Cc / 2);
    float2 v0 = __half22float2(ib[i00]);
    float2 v1 = __half22float2(ib[i00 + Cc / 2]);
    float2 v2 = __half22float2(ib[i00 + rs]);
    float2 v3 = __half22float2(ib[i00 + rs + Cc / 2]);
    float2 s;
    s.x = 0.25f * (v0.x + v1.x + v2.x + v3.x);
    s.y = 0.25f * (v0.y + v1.y + v2.y + v3.y);
    ((__half2*)(out + ((size_t)b * HoWo + p) * Cc))[c] = __floats2half2_rn(s.x, s.y);
}

// ---------------------------------------------------------------------------
// Correlation lookup via tensor cores. One block = one query pixel,
// 128 threads = 4 warps.
// Per level: the 100-position window is a GEMV [100x256]·[256] done as
// mma.sync m16n8k16 (query replicated across n=8; col 0 extracted).
// Positions are gathered into SMEM in two phases (rows 0-63, 64-111) to
// stay within static SMEM. Accumulators fp32; inputs fp16.
// ---------------------------------------------------------------------------
constexpr int ASTR = 264;   // halves per staged row (528B: 16B-aligned, bank-shifted)

__global__ __launch_bounds__(128) void lookup_k(const float* __restrict__ coords) {
    __shared__ __half   sA[64 * ASTR];    // 33792 B staging (64 positions)
    __shared__ __half   sQ[256];          // query fp16
    __shared__ float    sD[100];          // window dots
    __shared__ float    sVal[112];        // validity * 1/sqrt(C), pads = 0
    __shared__ unsigned sOff[112];        // clamped column offsets (half units)

    int n   = blockIdx.x;
    int b   = n / HWv;
    int rem = n - b * HWv;
    int t    = threadIdx.x;
    int w    = t >> 5;
    int lane = t & 31;

    // load query (512B) into SMEM
    ((unsigned*)sQ)[t] = ((const unsigned*)(g_f1h + (size_t)n * Cc))[t];

    float cx = coords[(size_t)b * 2 * HWv + rem];
    float cy = coords[(size_t)b * 2 * HWv + HWv + rem];

    const __half* lp[4] = { g_f20, g_f21, g_f22, g_f23 };
    const int Hs[4] = { Hh, H1, H2, H3 };
    const int Ws[4] = { Ww, W1, W2, W3 };

    unsigned sA_b = (unsigned)__cvta_generic_to_shared(sA);

#pragma unroll 1
    for (int l = 0; l < 4; l++) {
        float inv = 1.0f / (float)(1 << l);
        float px = cx * inv, py = cy * inv;
        float fx = floorf(px), fy = floorf(py);
        int x0 = (int)fx, y0 = (int)fy;
        float wx = px - fx, wy = py - fy;
        int Hl = Hs[l], Wl = Ws[l];
        const __half* base = lp[l] + (size_t)b * Hl * Wl * Cc;

        // precompute clamped offsets + validity for all 112 (padded) positions
        if (t < 112) {
            int p  = t;
            int pc = min(p, 99);
            int xi = pc / 10, yj = pc - xi * 10;
            int gx = x0 - 4 + xi, gy = y0 - 4 + yj;
            bool valid = (gx >= 0) & (gx < Wl) & (gy >= 0) & (gy < Hl) & (p < 100);
            int cgx = min(max(gx, 0), Wl - 1);
            int cgy = min(max(gy, 0), Hl - 1);
            sOff[t] = (unsigned)((cgy * Wl + cgx) * Cc);
            sVal[t] = valid ? 0.0625f : 0.0f;   // fold 1/sqrt(256)
        }
        __syncthreads();

        float acc1[4] = {0.f, 0.f, 0.f, 0.f};
        float acc2[4] = {0.f, 0.f, 0.f, 0.f};

        // ---- phase 1: stage positions 0..63, GEMM tiles 0..3 ----
#pragma unroll
        for (int i = 0; i < 16; i++) {
            int c = 4 * i + w;
            const uint4* src = (const uint4*)(base + sOff[c]);
            ((uint4*)(sA + c * ASTR))[lane] = src[lane];
        }
        __syncthreads();
        {
            unsigned arow = sA_b + (unsigned)(((w * 16 + (lane & 15)) * ASTR
                                    + ((lane >> 4) << 3)) * 2);
#pragma unroll
            for (int ks = 0; ks < 16; ks++) {
                unsigned a0, a1, a2, a3;
                asm volatile(
                    "ldmatrix.sync.aligned.m8n8.x4.shared.b16 {%0,%1,%2,%3}, [%4];"
                    : "=r"(a0), "=r"(a1), "=r"(a2), "=r"(a3)
                    : "r"(arow + (unsigned)(ks * 32)));
                unsigned bq0 = *(const unsigned*)&sQ[ks * 16 + 2 * (lane & 3)];
                unsigned bq1 = *(const unsigned*)&sQ[ks * 16 + 2 * (lane & 3) + 8];
                asm volatile(
                    "mma.sync.aligned.m16n8k16.row.col.f32.f16.f16.f32 "
                    "{%0,%1,%2,%3}, {%4,%5,%6,%7}, {%8,%9}, {%0,%1,%2,%3};"
                    : "+f"(acc1[0]), "+f"(acc1[1]), "+f"(acc1[2]), "+f"(acc1[3])
                    : "r"(a0), "r"(a1), "r"(a2), "r"(a3), "r"(bq0), "r"(bq1));
            }
        }
        __syncthreads();

        // ---- phase 2: stage positions 64..111 (local rows 0..47), tiles 4..6 ----
#pragma unroll
        for (int i = 0; i < 12; i++) {
            int c = 64 + 4 * i + w;
            const uint4* src = (const uint4*)(base + sOff[c]);
            ((uint4*)(sA + (c - 64) * ASTR))[lane] = src[lane];
        }
        __syncthreads();
        if (w < 3) {
            unsigned arow = sA_b + (unsigned)(((w * 16 + (lane & 15)) * ASTR
                                    + ((lane >> 4) << 3)) * 2);
#pragma unroll
            for (int ks = 0; ks < 16; ks++) {
                unsigned a0, a1, a2, a3;
                asm volatile(
                    "ldmatrix.sync.aligned.m8n8.x4.shared.b16 {%0,%1,%2,%3}, [%4];"
                    : "=r"(a0), "=r"(a1), "=r"(a2), "=r"(a3)
                    : "r"(arow + (unsigned)(ks * 32)));
                unsigned bq0 = *(const unsigned*)&sQ[ks * 16 + 2 * (lane & 3)];
                unsigned bq1 = *(const unsigned*)&sQ[ks * 16 + 2 * (lane & 3) + 8];
                asm volatile(
                    "mma.sync.aligned.m16n8k16.row.col.f32.f16.f16.f32 "
                    "{%0,%1,%2,%3}, {%4,%5,%6,%7}, {%8,%9}, {%0,%1,%2,%3};"
                    : "+f"(acc2[0]), "+f"(acc2[1]), "+f"(acc2[2]), "+f"(acc2[3])
                    : "r"(a0), "r"(a1), "r"(a2), "r"(a3), "r"(bq0), "r"(bq1));
            }
        }

        // ---- extraction: col 0 lives in lanes with lane%4==0 (c0 and c2) ----
        if ((lane & 3) == 0) {
            int r0 = w * 16 + (lane >> 2);
            sD[r0]     = acc1[0] * sVal[r0];
            sD[r0 + 8] = acc1[2] * sVal[r0 + 8];
            if (w < 3) {
                int g0 = 64 + w * 16 + (lane >> 2);
                int g1 = g0 + 8;
                if (g0 < 100) sD[g0] = acc2[0] * sVal[g0];
                if (g1 < 100) sD[g1] = acc2[2] * sVal[g1];
            }
        }
        __syncthreads();

        // ---- bilinear combine (81 outputs) ----
        if (t < 81) {
            int ix = t / 9, iy = t - ix * 9;
            float d00 = sD[ix * 10 + iy];
            float d10 = sD[ix * 10 + 10 + iy];
            float d01 = sD[ix * 10 + iy + 1];
            float d11 = sD[ix * 10 + 11 + iy];
            float v = (1.f - wy) * ((1.f - wx) * d00 + wx * d10)
                    +        wy  * ((1.f - wx) * d01 + wx * d11);
            g_corr[(size_t)n * 324 + l * 81 + t] = v;
        }
        __syncthreads();
    }
}

// ---------------------------------------------------------------------------
// Transpose compact corr [B*HW][324] -> out [B][324][HW] (coalesced both sides)
// ---------------------------------------------------------------------------
__global__ void corr_t_k(float* __restrict__ out) {
    __shared__ float tile[32][33];
    int b  = blockIdx.z;
    int r0 = blockIdx.x * 32;   // rem tile
    int c0 = blockIdx.y * 32;   // channel tile (0..323)
    int tx = threadIdx.x, ty = threadIdx.y;   // 32 x 8
#pragma unroll
    for (int r = 0; r < 32; r += 8) {
        int c = c0 + tx;
        float v = 0.f;
        if (c < 324)
            v = g_corr[((size_t)b * HWv + r0 + ty + r) * 324 + c];
        tile[ty + r][tx] = v;
    }
    __syncthreads();
#pragma unroll
    for (int r = 0; r < 32; r += 8) {
        int c = c0 + ty + r;
        if (c < 324)
            out[((size_t)b * 324 + c) * HWv + r0 + tx] = tile[tx][ty + r];
    }
}

// ---------------------------------------------------------------------------
// Convex upsample, coalesced. One block = 32 consecutive coarse pixels in a
// row. 256 threads: warp = subpixel row p8, lane = pixel.
// ---------------------------------------------------------------------------
__global__ __launch_bounds__(256) void upsample_k(const float* __restrict__ flow,
                                                  const float* __restrict__ mask,
                                                  float* __restrict__ out) {
    int rem0 = blockIdx.x * 32;
    int b  = rem0 / HWv;
    int r  = rem0 - b * HWv;
    int y  = r / Ww;
    int x0 = r - y * Ww;

    __shared__ float pfc[2][3][34];   // 3x3 neighborhoods of 8*flow for 32 pixels
    int t = threadIdx.x;
    if (t < 204) {
        int ch = t / 102, q = t - ch * 102;
        int dy = q / 34,  dx = q - dy * 34;
        int gy = y - 1 + dy, gx = x0 - 1 + dx;
        float v = 0.f;
        if (gy >= 0 && gy < Hh && gx >= 0 && gx < Ww)
            v = 8.f * flow[((size_t)b * 2 + ch) * HWv + gy * Ww + gx];
        pfc[ch][dy][dx] = v;
    }
    __syncthreads();

    int w = t >> 5;        // p8 (subpixel row)
    int lane = t & 31;     // pixel within the 32-pixel strip
    int rem = r + lane;
    const float* mb = mask + (size_t)b * 576 * HWv + rem;

    float o0[8], o1[8];
#pragma unroll
    for (int q8 = 0; q8 < 8; q8++) {
        float mv[9];
        float mmax = -1e30f;
#pragma unroll
        for (int k = 0; k < 9; k++) {
            mv[k] = mb[(size_t)(k * 64 + w * 8 + q8) * HWv];
            mmax = fmaxf(mmax, mv[k]);
        }
        float se = 0.f;
#pragma unroll
        for (int k = 0; k < 9; k++) { mv[k] = __expf(mv[k] - mmax); se += mv[k]; }
        float rr = 1.f / se;
        float s0 = 0.f, s1 = 0.f;
#pragma unroll
        for (int k = 0; k < 9; k++) {
            int i = k / 3, j = k - i * 3;
            s0 += mv[k] * pfc[0][i][lane + j];
            s1 += mv[k] * pfc[1][i][lane + j];
        }
        o0[q8] = s0 * rr;
        o1[q8] = s1 * rr;
    }

    size_t OFFU  = (size_t)Bb * 324 * HWv;
    size_t plane = (size_t)(Hh * 8) * (Ww * 8);
    int oy = y * 8 + w;
    float* p0 = out + OFFU + (size_t)b * 2 * plane
              + (size_t)oy * (Ww * 8) + (size_t)(x0 + lane) * 8;
    ((float4*)p0)[0] = make_float4(o0[0], o0[1], o0[2], o0[3]);
    ((float4*)p0)[1] = make_float4(o0[4], o0[5], o0[6], o0[7]);
    float* p1 = p0 + plane;
    ((float4*)p1)[0] = make_float4(o1[0], o1[1], o1[2], o1[3]);
    ((float4*)p1)[1] = make_float4(o1[4], o1[5], o1[6], o1[7]);
}

// ---------------------------------------------------------------------------
extern "C" void kernel_launch(void* const* d_in, const int* in_sizes, int n_in,
                              void* d_out, int out_size) {
    const float* fmap1  = (const float*)d_in[0];
    const float* fmap2  = (const float*)d_in[1];
    const float* coords = (const float*)d_in[2];
    const float* flow   = (const float*)d_in[3];
    const float* mask   = (const float*)d_in[4];
    float* out = (float*)d_out;

    dim3 tb(32, 8);
    dim3 tg(HWv / 32, Cc / 32, Bb);
    transpose_h_k<<<tg, tb>>>(fmap1, 0);
    transpose_h_k<<<tg, tb>>>(fmap2, 1);
    pool_k<<<dim3(H1 * W1, Bb), 128>>>(1);
    pool_k<<<dim3(H2 * W2, Bb), 128>>>(2);
    pool_k<<<dim3(H3 * W3, Bb), 128>>>(3);
    lookup_k<<<Nn, 128>>>(coords);
    corr_t_k<<<dim3(HWv / 32, 11, Bb), tb>>>(out);
    upsample_k<<<Nn / 32, 256>>>(flow, mask, out);
}